// round 15
// baseline (speedup 1.0000x reference)
#include <cuda_runtime.h>
#include <cuda_fp16.h>
#include <mma.h>
#include <math.h>
#include <stdint.h>

using namespace nvcuda;

#define BATCH 8
#define TT    9
#define CH    128
#define NPTS  1024
#define PAIRS 64
#define NFRAMES 72
#define NPASS 32
#define ROWBLKS 16

#define SINK_DYN (34816 + 33280)   // staging ring (2x64x136 fp16) + E tile (128x65 fp32)

// ---------------- device scratch (static: no runtime allocation) ----------------
__device__ __half  d_Ch[67108864];        // cost matrix fp16 (128 MB)
__device__ __half  d_xh[NFRAMES * NPTS * CH];
__device__ float  d_sq[NFRAMES * NPTS];
__device__ float  d_chmin[CH], d_chmax[CH];
__device__ float  d_eps_pass[NPASS];
__device__ float  d_f[2][PAIRS * NPTS];
__device__ float  d_g[2][PAIRS * NPTS];
__device__ float  d_psum[PAIRS * ROWBLKS * NPTS];  // col partials: psum_j * 2^(-g_j/eps') = sum_i 2^((f_i-C_ij)/eps')
__device__ double d_loss;
__device__ unsigned int d_ctr = 0;        // minmax completion counter (wraps -> replay-safe)

__device__ __forceinline__ float ex2f_(float x) {
    float r; asm("ex2.approx.ftz.f32 %0, %1;" : "=f"(r) : "f"(x)); return r;
}
__device__ __forceinline__ float lg2f_(float x) {
    float r; asm("lg2.approx.f32 %0, %1;" : "=f"(r) : "f"(x)); return r;
}
__device__ __forceinline__ void cp16(unsigned int dst, const void* src) {
    asm volatile("cp.async.cg.shared.global [%0], [%1], 16;" :: "r"(dst), "l"(src) : "memory");
}

#define GP(c) ((c) + ((c) >> 5))

// ---------------- per-channel min/max + (last CTA) eps schedule ----------------
__global__ void smm_minmax_kernel(const float* __restrict__ seq) {
    int c = blockIdx.x, tid = threadIdx.x;
    float mn = 3.4e38f, mx = -3.4e38f;
    for (int i = tid; i < NFRAMES * NPTS; i += 256) {
        int bt = i >> 10, n = i & 1023;
        float v = seq[((size_t)bt * CH + c) * NPTS + n];
        mn = fminf(mn, v); mx = fmaxf(mx, v);
    }
    __shared__ float smn[256], smx[256];
    smn[tid] = mn; smx[tid] = mx; __syncthreads();
    for (int s = 128; s > 0; s >>= 1) {
        if (tid < s) { smn[tid] = fminf(smn[tid], smn[tid + s]);
                       smx[tid] = fmaxf(smx[tid], smx[tid + s]); }
        __syncthreads();
    }
    if (tid == 0) {
        d_chmin[c] = smn[0]; d_chmax[c] = smx[0];
        __threadfence();
        unsigned int v = atomicInc(&d_ctr, CH - 1);
        if (v == CH - 1) {          // last CTA computes the schedule
            float ss = 0.f;
            for (int k = 0; k < CH; k++) {
                float dd = d_chmax[k] - d_chmin[k];
                ss += dd * dd;
            }
            float diam = sqrtf(ss) + 1e-6f;
            double ld = log((double)diam);
            double lb = log(0.1);
            d_eps_pass[0] = (float)exp(2.0 * ld);
            for (int k = 0; k < 30; k++) {
                double frac = (double)k / 29.0;
                d_eps_pass[k + 1] = (float)exp(2.0 * (ld + frac * (lb - ld)));
            }
            d_eps_pass[31] = 0.01f;
            d_loss = 0.0;
        }
    }
}

// ---------------- fused: fp16 point-major convert + squared norms; grid (72,4) ----------------
__global__ void smm_sqcvt_kernel(const float* __restrict__ seq) {
    __shared__ float ts[32][65];
    __shared__ float prt[256];
    int bt = blockIdx.x, qn = blockIdx.y, tid = threadIdx.x;
    const float* src = seq + (size_t)bt * CH * NPTS;
    __half* dst = d_xh + (size_t)bt * NPTS * CH;
    for (int nb = 0; nb < 4; nb++) {
        int nbase = (qn << 8) + (nb << 6);
        float sqp = 0.f;                       // this thread's n = tid&63, channels tid>>6 + 4k
        for (int cb4 = 0; cb4 < 4; cb4++) {
            int cb = cb4 << 5;
            #pragma unroll
            for (int it = 0; it < 8; it++) {
                int idx = tid + (it << 8);
                int c = idx >> 6, n = idx & 63;
                float v = src[(size_t)(cb + c) * NPTS + nbase + n];
                ts[c][n] = v;
                sqp = fmaf(v, v, sqp);
            }
            __syncthreads();
            #pragma unroll
            for (int it = 0; it < 4; it++) {
                int idx = tid + (it << 8);
                int n = idx >> 4, c2 = (idx & 15) << 1;
                __half2 h = __floats2half2_rn(ts[c2][n], ts[c2 + 1][n]);
                *(__half2*)&dst[(size_t)(nbase + n) * CH + cb + c2] = h;
            }
            __syncthreads();
        }
        prt[tid] = sqp; __syncthreads();
        if (tid < 64)
            d_sq[bt * NPTS + nbase + tid] =
                prt[tid] + prt[tid + 64] + prt[tid + 128] + prt[tid + 192];
        __syncthreads();
    }
}

// ---------------- cost matrix via wmma fp16 tensor cores, fp32 accumulate ----------------
__global__ void __launch_bounds__(256) smm_costmm_kernel() {
    __shared__ __align__(16) __half Asm[128 * 40];
    __shared__ __align__(16) __half Bsm[128 * 40];
    __shared__ __align__(16) float  scr[8][16 * 20];
    __shared__ float sxs[128], sys[128];

    int p = blockIdx.z, b = p >> 3, tt = p & 7;
    int fx = b * TT + tt, fy = fx + 1;
    int i0 = blockIdx.y * 128, j0 = blockIdx.x * 128;
    int tid = threadIdx.x, w = tid >> 5, l = tid & 31;
    int wm = (w >> 1) * 32, wn = (w & 1) * 64;

    if (tid < 128) sxs[tid] = d_sq[fx * NPTS + i0 + tid];
    else           sys[tid - 128] = d_sq[fy * NPTS + j0 + tid - 128];

    wmma::fragment<wmma::accumulator, 16, 16, 16, float> acc[2][4];
    #pragma unroll
    for (int tm = 0; tm < 2; tm++)
        #pragma unroll
        for (int tn = 0; tn < 4; tn++)
            wmma::fill_fragment(acc[tm][tn], 0.0f);

    const __half* Xg = d_xh + (size_t)fx * NPTS * CH;
    const __half* Yg = d_xh + (size_t)fy * NPTS * CH;

    for (int kc = 0; kc < 4; kc++) {
        int k0 = kc * 32;
        #pragma unroll
        for (int q = 0; q < 2; q++) {
            int u = tid + (q << 8);
            int row = u >> 2, c8 = (u & 3) << 3;
            *(uint4*)&Asm[row * 40 + c8] = *(const uint4*)&Xg[(size_t)(i0 + row) * CH + k0 + c8];
            *(uint4*)&Bsm[row * 40 + c8] = *(const uint4*)&Yg[(size_t)(j0 + row) * CH + k0 + c8];
        }
        __syncthreads();
        #pragma unroll
        for (int ks = 0; ks < 2; ks++) {
            wmma::fragment<wmma::matrix_a, 16, 16, 16, __half, wmma::row_major> af[2];
            wmma::fragment<wmma::matrix_b, 16, 16, 16, __half, wmma::col_major> bf[4];
            #pragma unroll
            for (int tm = 0; tm < 2; tm++)
                wmma::load_matrix_sync(af[tm], &Asm[(wm + tm * 16) * 40 + ks * 16], 40);
            #pragma unroll
            for (int tn = 0; tn < 4; tn++)
                wmma::load_matrix_sync(bf[tn], &Bsm[(wn + tn * 16) * 40 + ks * 16], 40);
            #pragma unroll
            for (int tm = 0; tm < 2; tm++)
                #pragma unroll
                for (int tn = 0; tn < 4; tn++)
                    wmma::mma_sync(acc[tm][tn], af[tm], bf[tn], acc[tm][tn]);
        }
        __syncthreads();
    }

    __half* Co = d_Ch + (size_t)p * NPTS * NPTS;
    int r = l >> 1, cb = (l & 1) << 3;
    #pragma unroll
    for (int tm = 0; tm < 2; tm++) {
        #pragma unroll
        for (int tn = 0; tn < 4; tn++) {
            wmma::store_matrix_sync(&scr[w][0], acc[tm][tn], 20, wmma::mem_row_major);
            __syncwarp();
            float sx = sxs[wm + tm * 16 + r];
            union { uint4 u4; __half2 h[4]; } pk;
            #pragma unroll
            for (int j = 0; j < 4; j++) {
                int c = cb + j * 2;
                float d0 = scr[w][r * 20 + c], d1 = scr[w][r * 20 + c + 1];
                float v0 = fmaxf(0.5f * (sx + sys[wn + tn * 16 + c]) - d0, 0.f);
                float v1 = fmaxf(0.5f * (sx + sys[wn + tn * 16 + c + 1]) - d1, 0.f);
                pk.h[j] = __floats2half2_rn(v0, v1);
            }
            *(uint4*)&Co[(size_t)(i0 + wm + tm * 16 + r) * NPTS + j0 + wn + tn * 16 + cb] = pk.u4;
            __syncwarp();
        }
    }
}

// ---------------- fused Sinkhorn sweep: cp.async pipeline + exp-reuse col sums ----------------
// Row: E_ij = 2^(v_ij - tlm_i) (one exp/element), row LSE via online merge.
// Col: psum_j = sum_i E_ij * a_i, a_i = 2^(tlm_i + f_i/eps')  -- NO exps per element.
// psum_j * 2^(-g_j/eps') = sum_i 2^((f_i - C_ij)/eps'); combine folds the g shift back.
// flags: bit0 zero-init pass, bit1 average f-update, bit2 final (loss) pass.
__global__ void __launch_bounds__(256, 2) smm_sink_kernel(int pass, int flags) {
    extern __shared__ __align__(16) char dyn[];
    __half (*st)[64 * 136] = (__half(*)[64 * 136])dyn;          // staging ring
    float* Es = (float*)(dyn + 34816);                           // E tile [128][65] col-major
    __shared__ float gsh[1056];
    __shared__ float fsh[64];
    __shared__ float fraw[64];
    __shared__ float arow[64];        // a_i = 2^(tlm_i + fsh_i), per tile
    __shared__ float red[256];
    int p = blockIdx.y, rb = blockIdx.x, tid = threadIdx.x;
    int zf = flags & 1, avg = flags & 2, fin = flags & 4;
    float eps = d_eps_pass[pass];
    float ivl = 1.4426950408889634f / eps;
    float nivl = -ivl;
    int r0 = rb * 64;
    const float* f_in = d_f[pass & 1];
    const float* g_in = d_g[pass & 1];
    float* f_out = d_f[(pass + 1) & 1];

    const __half* Cph = d_Ch + (size_t)p * 1048576 + (size_t)r0 * 1024;
    unsigned int stb = (unsigned int)__cvta_generic_to_shared(&st[0][0]);

    // issue tile 0 into buffer 0
    #pragma unroll
    for (int q = 0; q < 4; q++) {
        int id = (q << 8) + tid, r = id >> 4, j8 = id & 15;
        cp16(stb + r * 272 + (j8 << 4), Cph + (size_t)r * 1024 + (j8 << 3));
    }
    asm volatile("cp.async.commit_group;" ::: "memory");

    for (int j = tid; j < 1024; j += 256) gsh[GP(j)] = zf ? 0.f : g_in[p * 1024 + j] * ivl;
    if (tid < 64) {
        float fv = zf ? 0.f : f_in[p * 1024 + r0 + tid];
        fraw[tid] = fv; fsh[tid] = fv * ivl;
    }

    int row = tid >> 2, part = tid & 3;      // row sweep: 64 rows x 4 lanes
    int ccol = tid >> 1, chalf = tid & 1;    // col sweep: 128 cols x 2 lanes
    int rowp = (row + (part << 3)) & 63;     // rotated E-store row
    int rrot = (ccol >> 5) << 3;             // E-read rotation (matches writer part = col>>5)
    float rm = -1e30f, rs = 0.f;

    for (int t8 = 0; t8 < 8; t8++) {
        int c0 = t8 << 7;
        if (t8 < 7) {
            int nb = (t8 + 1) & 1;
            #pragma unroll
            for (int q = 0; q < 4; q++) {
                int id = (q << 8) + tid, r = id >> 4, j8 = id & 15;
                cp16(stb + nb * 17408 + r * 272 + (j8 << 4),
                     Cph + (size_t)r * 1024 + c0 + 128 + (j8 << 3));
            }
            asm volatile("cp.async.commit_group;" ::: "memory");
            asm volatile("cp.async.wait_group 1;" ::: "memory");
        } else {
            asm volatile("cp.async.wait_group 0;" ::: "memory");
        }
        __syncthreads();

        const __half2* S = (const __half2*)&st[t8 & 1][0];   // row stride 68 words
        // ---- row phase: v, tile-local row max, E, row LSE merge ----
        float v[32]; float lm = -1e30f;
        #pragma unroll
        for (int q = 0; q < 16; q++) {
            int qr = (q + part * 5) & 15;                    // stride-5 rotation: conflict-free
            int h2i = (part << 4) + qr;
            float2 cv = __half22float2(S[row * 68 + h2i]);
            int colp = c0 + (h2i << 1);
            float x0 = fmaf(cv.x, nivl, gsh[GP(colp)]);
            float x1 = fmaf(cv.y, nivl, gsh[GP(colp + 1)]);
            v[qr * 2] = x0; v[qr * 2 + 1] = x1;
            lm = fmaxf(lm, fmaxf(x0, x1));
        }
        lm = fmaxf(lm, __shfl_xor_sync(0xffffffffu, lm, 1));
        lm = fmaxf(lm, __shfl_xor_sync(0xffffffffu, lm, 2));
        float tlm = lm;                                      // row max over this tile's 128 cols
        float ls = 0.f;
        #pragma unroll
        for (int k = 0; k < 32; k++) {
            float e = ex2f_(v[k] - tlm);
            v[k] = e; ls += e;
        }
        ls += __shfl_xor_sync(0xffffffffu, ls, 1);
        ls += __shfl_xor_sync(0xffffffffu, ls, 2);
        float nm = fmaxf(rm, tlm);
        rs = rs * ex2f_(rm - nm) + ls * ex2f_(tlm - nm); rm = nm;
        // store E transposed (rotated, conflict-free) + per-row factor a_i
        #pragma unroll
        for (int k = 0; k < 32; k++)
            Es[((part << 5) + k) * 65 + rowp] = v[k];
        if (part == 0) arow[row] = ex2f_(tlm + fsh[row]);    // <= 2^~12: no overflow
        __syncthreads();

        // ---- col phase: pure FMA sums ----
        float csum = 0.f;
        #pragma unroll
        for (int k = 0; k < 32; k++) {
            int rr = (chalf << 5) + ((k + (chalf << 4)) & 31);
            float e = Es[ccol * 65 + ((rr + rrot) & 63)];
            csum = fmaf(e, arow[rr], csum);
        }
        csum += __shfl_xor_sync(0xffffffffu, csum, 1);
        if (chalf == 0)
            d_psum[(p * ROWBLKS + rb) * 1024 + c0 + ccol] = csum;
        __syncthreads();
    }
    float ft = -eps * 0.69314718055994531f * (rm + lg2f_(rs) - 10.f);
    if (!fin) {
        if (part == 0) f_out[p * 1024 + r0 + row] = avg ? 0.5f * (fraw[row] + ft) : ft;
    } else {
        red[tid] = (part == 0) ? ft : 0.f;
        __syncthreads();
        for (int s = 128; s > 0; s >>= 1) {
            if (tid < s) red[tid] += red[tid + s];
            __syncthreads();
        }
        if (tid == 0) atomicAdd(&d_loss, (double)red[0]);
    }
}

// ---------------- merge 16 row-strip col sums -> gt_j = g_j - eps*ln2*(log2 S - 10) ----------------
__global__ void smm_combine_kernel(int pass, int flags) {
    int gid = blockIdx.x * 256 + threadIdx.x;
    int p = gid >> 10, col = gid & 1023;
    const float* g_in = d_g[pass & 1];
    float* g_out = d_g[(pass + 1) & 1];
    int zf = flags & 1, avg = flags & 2, fin = flags & 4;
    float eps = d_eps_pass[pass];
    float S = 0.f;
    #pragma unroll
    for (int b2 = 0; b2 < ROWBLKS; b2++)
        S += d_psum[(p * ROWBLKS + b2) * 1024 + col];
    float gprev = zf ? 0.f : g_in[gid];
    float gt = gprev - eps * 0.69314718055994531f * (lg2f_(S) - 10.f);
    if (!fin) {
        g_out[gid] = avg ? 0.5f * (gprev + gt) : gt;
    } else {
        __shared__ float red[256];
        red[threadIdx.x] = gt; __syncthreads();
        for (int s = 128; s > 0; s >>= 1) {
            if (threadIdx.x < s) red[threadIdx.x] += red[threadIdx.x + s];
            __syncthreads();
        }
        if (threadIdx.x == 0) atomicAdd(&d_loss, (double)red[0]);
    }
}

__global__ void smm_finalize_kernel(float* out, int n) {
    float v = (float)(d_loss * (1.0 / 65536.0));   // /(P*N)
    for (int i = threadIdx.x; i < n; i += 32) out[i] = v;
}

// ---------------- launch: graph-capturable, no allocs, no sync ----------------
extern "C" void kernel_launch(void* const* d_in, const int* in_sizes, int n_in,
                              void* d_out, int out_size) {
    const float* seq = (const float*)d_in[0];
    cudaFuncSetAttribute(smm_sink_kernel, cudaFuncAttributeMaxDynamicSharedMemorySize, SINK_DYN);
    smm_minmax_kernel<<<CH, 256>>>(seq);                 // 1 (+ eps schedule via last CTA)
    smm_sqcvt_kernel<<<dim3(NFRAMES, 4), 256>>>(seq);    // 2
    smm_costmm_kernel<<<dim3(8, 8, PAIRS), 256>>>();     // 3
    for (int pass = 0; pass < NPASS; ++pass) {           // 4 = first sink (ncu captures it)
        int flags = (pass == 0 ? 1 : 0)
                  | ((pass >= 1 && pass <= 30) ? 2 : 0)
                  | (pass == 31 ? 4 : 0);
        smm_sink_kernel<<<dim3(ROWBLKS, PAIRS), 256, SINK_DYN>>>(pass, flags);
        smm_combine_kernel<<<PAIRS * NPTS / 256, 256>>>(pass, flags);
    }
    smm_finalize_kernel<<<1, 32>>>((float*)d_out, out_size);
}

// round 16
// speedup vs baseline: 3.0707x; 3.0707x over previous
#include <cuda_runtime.h>
#include <cuda_fp16.h>
#include <mma.h>
#include <math.h>
#include <stdint.h>

using namespace nvcuda;

#define BATCH 8
#define TT    9
#define CH    128
#define NPTS  1024
#define PAIRS 64
#define NFRAMES 72
#define NPASS 32
#define ROWBLKS 16

#define SINK_DYN (34816 + 33280)   // staging ring (2x64x136 fp16) + E tile (128x65 fp32)

// ---------------- device scratch (static: no runtime allocation) ----------------
__device__ __half  d_Ch[67108864];        // cost matrix fp16 (128 MB)
__device__ __half  d_xh[NFRAMES * NPTS * CH];
__device__ float  d_sq[NFRAMES * NPTS];
__device__ float  d_chmin[CH], d_chmax[CH];
__device__ float  d_eps_pass[NPASS];
__device__ float  d_f[2][PAIRS * NPTS];
__device__ float  d_g[2][PAIRS * NPTS];
__device__ float  d_psum[PAIRS * ROWBLKS * NPTS];  // col partials (g-shift folded into combine)
__device__ double d_loss;
__device__ unsigned int d_ctr = 0;        // minmax completion counter (wraps -> replay-safe)

__device__ __forceinline__ float ex2f_(float x) {
    float r; asm("ex2.approx.ftz.f32 %0, %1;" : "=f"(r) : "f"(x)); return r;
}
__device__ __forceinline__ float lg2f_(float x) {
    float r; asm("lg2.approx.f32 %0, %1;" : "=f"(r) : "f"(x)); return r;
}
__device__ __forceinline__ void cp16(unsigned int dst, const void* src) {
    asm volatile("cp.async.cg.shared.global [%0], [%1], 16;" :: "r"(dst), "l"(src) : "memory");
}

#define GP(c) ((c) + ((c) >> 5))

// ---------------- per-channel min/max + (last CTA) eps schedule ----------------
__global__ void smm_minmax_kernel(const float* __restrict__ seq) {
    int c = blockIdx.x, tid = threadIdx.x;
    float mn = 3.4e38f, mx = -3.4e38f;
    for (int i = tid; i < NFRAMES * NPTS; i += 256) {
        int bt = i >> 10, n = i & 1023;
        float v = seq[((size_t)bt * CH + c) * NPTS + n];
        mn = fminf(mn, v); mx = fmaxf(mx, v);
    }
    __shared__ float smn[256], smx[256];
    smn[tid] = mn; smx[tid] = mx; __syncthreads();
    for (int s = 128; s > 0; s >>= 1) {
        if (tid < s) { smn[tid] = fminf(smn[tid], smn[tid + s]);
                       smx[tid] = fmaxf(smx[tid], smx[tid + s]); }
        __syncthreads();
    }
    if (tid == 0) {
        d_chmin[c] = smn[0]; d_chmax[c] = smx[0];
        __threadfence();
        unsigned int v = atomicInc(&d_ctr, CH - 1);
        if (v == CH - 1) {          // last CTA computes the schedule
            float ss = 0.f;
            for (int k = 0; k < CH; k++) {
                float dd = d_chmax[k] - d_chmin[k];
                ss += dd * dd;
            }
            float diam = sqrtf(ss) + 1e-6f;
            double ld = log((double)diam);
            double lb = log(0.1);
            d_eps_pass[0] = (float)exp(2.0 * ld);
            for (int k = 0; k < 30; k++) {
                double frac = (double)k / 29.0;
                d_eps_pass[k + 1] = (float)exp(2.0 * (ld + frac * (lb - ld)));
            }
            d_eps_pass[31] = 0.01f;
            d_loss = 0.0;
        }
    }
}

// ---------------- fused: fp16 point-major convert + squared norms; grid (72,4) ----------------
__global__ void smm_sqcvt_kernel(const float* __restrict__ seq) {
    __shared__ float ts[32][65];
    __shared__ float prt[256];
    int bt = blockIdx.x, qn = blockIdx.y, tid = threadIdx.x;
    const float* src = seq + (size_t)bt * CH * NPTS;
    __half* dst = d_xh + (size_t)bt * NPTS * CH;
    for (int nb = 0; nb < 4; nb++) {
        int nbase = (qn << 8) + (nb << 6);
        float sqp = 0.f;
        for (int cb4 = 0; cb4 < 4; cb4++) {
            int cb = cb4 << 5;
            #pragma unroll
            for (int it = 0; it < 8; it++) {
                int idx = tid + (it << 8);
                int c = idx >> 6, n = idx & 63;
                float v = src[(size_t)(cb + c) * NPTS + nbase + n];
                ts[c][n] = v;
                sqp = fmaf(v, v, sqp);
            }
            __syncthreads();
            #pragma unroll
            for (int it = 0; it < 4; it++) {
                int idx = tid + (it << 8);
                int n = idx >> 4, c2 = (idx & 15) << 1;
                __half2 h = __floats2half2_rn(ts[c2][n], ts[c2 + 1][n]);
                *(__half2*)&dst[(size_t)(nbase + n) * CH + cb + c2] = h;
            }
            __syncthreads();
        }
        prt[tid] = sqp; __syncthreads();
        if (tid < 64)
            d_sq[bt * NPTS + nbase + tid] =
                prt[tid] + prt[tid + 64] + prt[tid + 128] + prt[tid + 192];
        __syncthreads();
    }
}

// ---------------- cost matrix via wmma fp16 tensor cores, fp32 accumulate ----------------
__global__ void __launch_bounds__(256) smm_costmm_kernel() {
    __shared__ __align__(16) __half Asm[128 * 40];
    __shared__ __align__(16) __half Bsm[128 * 40];
    __shared__ __align__(16) float  scr[8][16 * 20];
    __shared__ float sxs[128], sys[128];

    int p = blockIdx.z, b = p >> 3, tt = p & 7;
    int fx = b * TT + tt, fy = fx + 1;
    int i0 = blockIdx.y * 128, j0 = blockIdx.x * 128;
    int tid = threadIdx.x, w = tid >> 5, l = tid & 31;
    int wm = (w >> 1) * 32, wn = (w & 1) * 64;

    if (tid < 128) sxs[tid] = d_sq[fx * NPTS + i0 + tid];
    else           sys[tid - 128] = d_sq[fy * NPTS + j0 + tid - 128];

    wmma::fragment<wmma::accumulator, 16, 16, 16, float> acc[2][4];
    #pragma unroll
    for (int tm = 0; tm < 2; tm++)
        #pragma unroll
        for (int tn = 0; tn < 4; tn++)
            wmma::fill_fragment(acc[tm][tn], 0.0f);

    const __half* Xg = d_xh + (size_t)fx * NPTS * CH;
    const __half* Yg = d_xh + (size_t)fy * NPTS * CH;

    for (int kc = 0; kc < 4; kc++) {
        int k0 = kc * 32;
        #pragma unroll
        for (int q = 0; q < 2; q++) {
            int u = tid + (q << 8);
            int row = u >> 2, c8 = (u & 3) << 3;
            *(uint4*)&Asm[row * 40 + c8] = *(const uint4*)&Xg[(size_t)(i0 + row) * CH + k0 + c8];
            *(uint4*)&Bsm[row * 40 + c8] = *(const uint4*)&Yg[(size_t)(j0 + row) * CH + k0 + c8];
        }
        __syncthreads();
        #pragma unroll
        for (int ks = 0; ks < 2; ks++) {
            wmma::fragment<wmma::matrix_a, 16, 16, 16, __half, wmma::row_major> af[2];
            wmma::fragment<wmma::matrix_b, 16, 16, 16, __half, wmma::col_major> bf[4];
            #pragma unroll
            for (int tm = 0; tm < 2; tm++)
                wmma::load_matrix_sync(af[tm], &Asm[(wm + tm * 16) * 40 + ks * 16], 40);
            #pragma unroll
            for (int tn = 0; tn < 4; tn++)
                wmma::load_matrix_sync(bf[tn], &Bsm[(wn + tn * 16) * 40 + ks * 16], 40);
            #pragma unroll
            for (int tm = 0; tm < 2; tm++)
                #pragma unroll
                for (int tn = 0; tn < 4; tn++)
                    wmma::mma_sync(acc[tm][tn], af[tm], bf[tn], acc[tm][tn]);
        }
        __syncthreads();
    }

    __half* Co = d_Ch + (size_t)p * NPTS * NPTS;
    int r = l >> 1, cb = (l & 1) << 3;
    #pragma unroll
    for (int tm = 0; tm < 2; tm++) {
        #pragma unroll
        for (int tn = 0; tn < 4; tn++) {
            wmma::store_matrix_sync(&scr[w][0], acc[tm][tn], 20, wmma::mem_row_major);
            __syncwarp();
            float sx = sxs[wm + tm * 16 + r];
            union { uint4 u4; __half2 h[4]; } pk;
            #pragma unroll
            for (int j = 0; j < 4; j++) {
                int c = cb + j * 2;
                float d0 = scr[w][r * 20 + c], d1 = scr[w][r * 20 + c + 1];
                float v0 = fmaxf(0.5f * (sx + sys[wn + tn * 16 + c]) - d0, 0.f);
                float v1 = fmaxf(0.5f * (sx + sys[wn + tn * 16 + c + 1]) - d1, 0.f);
                pk.h[j] = __floats2half2_rn(v0, v1);
            }
            *(uint4*)&Co[(size_t)(i0 + wm + tm * 16 + r) * NPTS + j0 + wn + tn * 16 + cb] = pk.u4;
            __syncwarp();
        }
    }
}

// ---------------- fused Sinkhorn sweep: cp.async pipeline + exp-reuse col sums ----------------
// Row: E_ij = 2^(v_ij - tlm_i) (one exp/element). Col: psum_j = sum_i E_ij * a_i (pure FMA).
// All register arrays indexed with compile-time indices; rotations applied to SMEM addresses.
// flags: bit0 zero-init pass, bit1 average f-update, bit2 final (loss) pass.
__global__ void __launch_bounds__(256, 2) smm_sink_kernel(int pass, int flags) {
    extern __shared__ __align__(16) char dyn[];
    __half (*st)[64 * 136] = (__half(*)[64 * 136])dyn;          // staging ring
    float* Es = (float*)(dyn + 34816);                           // E tile [128][65] col-major
    __shared__ float gsh[1056];
    __shared__ float fsh[64];
    __shared__ float fraw[64];
    __shared__ float arow[64];        // a_i = 2^(tlm_i + fsh_i), per tile
    __shared__ float red[256];
    int p = blockIdx.y, rb = blockIdx.x, tid = threadIdx.x;
    int zf = flags & 1, avg = flags & 2, fin = flags & 4;
    float eps = d_eps_pass[pass];
    float ivl = 1.4426950408889634f / eps;
    float nivl = -ivl;
    int r0 = rb * 64;
    const float* f_in = d_f[pass & 1];
    const float* g_in = d_g[pass & 1];
    float* f_out = d_f[(pass + 1) & 1];

    const __half* Cph = d_Ch + (size_t)p * 1048576 + (size_t)r0 * 1024;
    unsigned int stb = (unsigned int)__cvta_generic_to_shared(&st[0][0]);

    // issue tile 0 into buffer 0
    #pragma unroll
    for (int q = 0; q < 4; q++) {
        int id = (q << 8) + tid, r = id >> 4, j8 = id & 15;
        cp16(stb + r * 272 + (j8 << 4), Cph + (size_t)r * 1024 + (j8 << 3));
    }
    asm volatile("cp.async.commit_group;" ::: "memory");

    for (int j = tid; j < 1024; j += 256) gsh[GP(j)] = zf ? 0.f : g_in[p * 1024 + j] * ivl;
    if (tid < 64) {
        float fv = zf ? 0.f : f_in[p * 1024 + r0 + tid];
        fraw[tid] = fv; fsh[tid] = fv * ivl;
    }

    int row = tid >> 2, part = tid & 3;      // row sweep: 64 rows x 4 lanes
    int ccol = tid >> 1, chalf = tid & 1;    // col sweep: 128 cols x 2 lanes
    int rowp = (row - 2 * part) & 63;        // E-store row rotation (banks 2q+8*part+row)
    int crot = 2 * (ccol >> 5);              // E-read inverse rotation (writer part = col>>5)
    float rm = -1e30f, rs = 0.f;

    for (int t8 = 0; t8 < 8; t8++) {
        int c0 = t8 << 7;
        if (t8 < 7) {
            int nb = (t8 + 1) & 1;
            #pragma unroll
            for (int q = 0; q < 4; q++) {
                int id = (q << 8) + tid, r = id >> 4, j8 = id & 15;
                cp16(stb + nb * 17408 + r * 272 + (j8 << 4),
                     Cph + (size_t)r * 1024 + c0 + 128 + (j8 << 3));
            }
            asm volatile("cp.async.commit_group;" ::: "memory");
            asm volatile("cp.async.wait_group 1;" ::: "memory");
        } else {
            asm volatile("cp.async.wait_group 0;" ::: "memory");
        }
        __syncthreads();

        const __half2* S = (const __half2*)&st[t8 & 1][0];   // row stride 68 words
        // ---- row phase: in-order registers, rotated smem addresses ----
        float v[32]; float lm = -1e30f;
        #pragma unroll
        for (int q = 0; q < 16; q++) {
            int h2i = (part << 4) + ((q + part * 5) & 15);   // stride-5 rotation (address only)
            float2 cv = __half22float2(S[row * 68 + h2i]);
            int colp = c0 + (h2i << 1);
            float x0 = fmaf(cv.x, nivl, gsh[GP(colp)]);
            float x1 = fmaf(cv.y, nivl, gsh[GP(colp + 1)]);
            v[q * 2] = x0; v[q * 2 + 1] = x1;                // compile-time indices
            lm = fmaxf(lm, fmaxf(x0, x1));
        }
        lm = fmaxf(lm, __shfl_xor_sync(0xffffffffu, lm, 1));
        lm = fmaxf(lm, __shfl_xor_sync(0xffffffffu, lm, 2));
        float tlm = lm;
        float ls = 0.f;
        #pragma unroll
        for (int k = 0; k < 32; k++) {
            float e = ex2f_(v[k] - tlm);
            v[k] = e; ls += e;
        }
        ls += __shfl_xor_sync(0xffffffffu, ls, 1);
        ls += __shfl_xor_sync(0xffffffffu, ls, 2);
        float nm = fmaxf(rm, tlm);
        rs = rs * ex2f_(rm - nm) + ls * ex2f_(tlm - nm); rm = nm;
        // ---- E store: same column mapping, rotated row (conflict-free) ----
        #pragma unroll
        for (int q = 0; q < 16; q++) {
            int h2i = (part << 4) + ((q + part * 5) & 15);
            int col0 = h2i << 1;
            Es[col0 * 65 + rowp]       = v[q * 2];
            Es[(col0 + 1) * 65 + rowp] = v[q * 2 + 1];
        }
        if (part == 0) arow[row] = ex2f_(tlm + fsh[row]);    // <= 2^~12: no overflow
        __syncthreads();

        // ---- col phase: pure FMA sums ----
        float csum = 0.f;
        #pragma unroll
        for (int k = 0; k < 32; k++) {
            int rr = (chalf << 5) + ((k + (chalf << 4)) & 31);
            float e = Es[ccol * 65 + ((rr - crot) & 63)];
            csum = fmaf(e, arow[rr], csum);
        }
        csum += __shfl_xor_sync(0xffffffffu, csum, 1);
        if (chalf == 0)
            d_psum[(p * ROWBLKS + rb) * 1024 + c0 + ccol] = csum;
        __syncthreads();
    }
    float ft = -eps * 0.69314718055994531f * (rm + lg2f_(rs) - 10.f);
    if (!fin) {
        if (part == 0) f_out[p * 1024 + r0 + row] = avg ? 0.5f * (fraw[row] + ft) : ft;
    } else {
        red[tid] = (part == 0) ? ft : 0.f;
        __syncthreads();
        for (int s = 128; s > 0; s >>= 1) {
            if (tid < s) red[tid] += red[tid + s];
            __syncthreads();
        }
        if (tid == 0) atomicAdd(&d_loss, (double)red[0]);
    }
}

// ---------------- merge 16 row-strip col sums -> gt_j = g_j - eps*ln2*(log2 S - 10) ----------------
__global__ void smm_combine_kernel(int pass, int flags) {
    int gid = blockIdx.x * 256 + threadIdx.x;
    int p = gid >> 10, col = gid & 1023;
    const float* g_in = d_g[pass & 1];
    float* g_out = d_g[(pass + 1) & 1];
    int zf = flags & 1, avg = flags & 2, fin = flags & 4;
    float eps = d_eps_pass[pass];
    float S = 0.f;
    #pragma unroll
    for (int b2 = 0; b2 < ROWBLKS; b2++)
        S += d_psum[(p * ROWBLKS + b2) * 1024 + col];
    float gprev = zf ? 0.f : g_in[gid];
    float gt = gprev - eps * 0.69314718055994531f * (lg2f_(S) - 10.f);
    if (!fin) {
        g_out[gid] = avg ? 0.5f * (gprev + gt) : gt;
    } else {
        __shared__ float red[256];
        red[threadIdx.x] = gt; __syncthreads();
        for (int s = 128; s > 0; s >>= 1) {
            if (threadIdx.x < s) red[threadIdx.x] += red[threadIdx.x + s];
            __syncthreads();
        }
        if (threadIdx.x == 0) atomicAdd(&d_loss, (double)red[0]);
    }
}

__global__ void smm_finalize_kernel(float* out, int n) {
    float v = (float)(d_loss * (1.0 / 65536.0));   // /(P*N)
    for (int i = threadIdx.x; i < n; i += 32) out[i] = v;
}

// ---------------- launch: graph-capturable, no allocs, no sync ----------------
extern "C" void kernel_launch(void* const* d_in, const int* in_sizes, int n_in,
                              void* d_out, int out_size) {
    const float* seq = (const float*)d_in[0];
    cudaFuncSetAttribute(smm_sink_kernel, cudaFuncAttributeMaxDynamicSharedMemorySize, SINK_DYN);
    smm_minmax_kernel<<<CH, 256>>>(seq);                 // 1 (+ eps schedule via last CTA)
    smm_sqcvt_kernel<<<dim3(NFRAMES, 4), 256>>>(seq);    // 2
    smm_costmm_kernel<<<dim3(8, 8, PAIRS), 256>>>();     // 3
    for (int pass = 0; pass < NPASS; ++pass) {           // 4 = first sink (ncu captures it)
        int flags = (pass == 0 ? 1 : 0)
                  | ((pass >= 1 && pass <= 30) ? 2 : 0)
                  | (pass == 31 ? 4 : 0);
        smm_sink_kernel<<<dim3(ROWBLKS, PAIRS), 256, SINK_DYN>>>(pass, flags);
        smm_combine_kernel<<<PAIRS * NPTS / 256, 256>>>(pass, flags);
    }
    smm_finalize_kernel<<<1, 32>>>((float*)d_out, out_size);
}